// round 1
// baseline (speedup 1.0000x reference)
#include <cuda_runtime.h>
#include <math.h>

#define BDIM 4
#define SEQ 1024
#define DMODEL 1024
#define NH 16
#define DH 64
#define SPAN 256
#define TWOSPAN 512
#define NBATCH (BDIM*NH)   /* 64 */

// ---------------- scratch (device globals; no allocation allowed) ----------
__device__ float g_q   [(size_t)NBATCH * SEQ * DH];        // 16 MB
__device__ float g_k   [(size_t)NBATCH * SEQ * DH];
__device__ float g_v   [(size_t)NBATCH * SEQ * DH];
__device__ float g_posk[(size_t)NH * TWOSPAN * DH];        // 2 MB
__device__ float g_posq[(size_t)NH * TWOSPAN * DH];
__device__ float g_c2p [(size_t)NBATCH * SEQ * TWOSPAN];   // 128 MB
__device__ float g_p2c [(size_t)NBATCH * SEQ * TWOSPAN];   // 128 MB
__device__ float g_sc  [(size_t)NBATCH * SEQ * SEQ];       // 256 MB
__device__ float g_ctx [(size_t)BDIM * SEQ * DMODEL];      // 16 MB

// ---------------- helpers ---------------------------------------------------
__device__ __forceinline__ int rel_bucket(int rel) {
    // mirrors build_rel_pos: mid=128, MAX_POS-1=511
    float abs_pos = (rel < 128 && rel > -128) ? 127.0f : fabsf((float)rel);
    if (abs_pos <= 128.0f) return rel;
    float sgn = (rel > 0) ? 1.0f : -1.0f;
    float log_pos = ceilf(logf(abs_pos * (1.0f/128.0f)) / logf(511.0f/128.0f) * 127.0f) + 128.0f;
    return (int)(log_pos * sgn);
}

__device__ __forceinline__ float block_sum(float v, float* sh) {
    #pragma unroll
    for (int o = 16; o; o >>= 1) v += __shfl_xor_sync(0xffffffffu, v, o);
    int lane = threadIdx.x & 31, w = threadIdx.x >> 5;
    __syncthreads();
    if (lane == 0) sh[w] = v;
    __syncthreads();
    int nw = blockDim.x >> 5;
    if (w == 0) {
        float x = (lane < nw) ? sh[lane] : 0.0f;
        #pragma unroll
        for (int o = 16; o; o >>= 1) x += __shfl_xor_sync(0xffffffffu, x, o);
        if (lane == 0) sh[0] = x;
    }
    __syncthreads();
    return sh[0];
}

__device__ __forceinline__ float block_max(float v, float* sh) {
    #pragma unroll
    for (int o = 16; o; o >>= 1) v = fmaxf(v, __shfl_xor_sync(0xffffffffu, v, o));
    int lane = threadIdx.x & 31, w = threadIdx.x >> 5;
    __syncthreads();
    if (lane == 0) sh[w] = v;
    __syncthreads();
    int nw = blockDim.x >> 5;
    if (w == 0) {
        float x = (lane < nw) ? sh[lane] : -INFINITY;
        #pragma unroll
        for (int o = 16; o; o >>= 1) x = fmaxf(x, __shfl_xor_sync(0xffffffffu, x, o));
        if (lane == 0) sh[0] = x;
    }
    __syncthreads();
    return sh[0];
}

// 64x64x16 fp32 tile core (ABt): As/Bs are [16][68] padded, 256 threads, 4x4/thread
#define TILE_COMPUTE(acc, As, Bs, ty, tx)                                        \
    _Pragma("unroll")                                                            \
    for (int kk = 0; kk < 16; kk++) {                                            \
        float4 a = *(const float4*)&As[kk][(ty) * 4];                            \
        float4 b = *(const float4*)&Bs[kk][(tx) * 4];                            \
        acc[0][0] += a.x*b.x; acc[0][1] += a.x*b.y; acc[0][2] += a.x*b.z; acc[0][3] += a.x*b.w; \
        acc[1][0] += a.y*b.x; acc[1][1] += a.y*b.y; acc[1][2] += a.y*b.z; acc[1][3] += a.y*b.w; \
        acc[2][0] += a.z*b.x; acc[2][1] += a.z*b.y; acc[2][2] += a.z*b.z; acc[2][3] += a.z*b.w; \
        acc[3][0] += a.w*b.x; acc[3][1] += a.w*b.y; acc[3][2] += a.w*b.z; acc[3][3] += a.w*b.w; \
    }

// ---------------- 1) projections: C = A[M,K] @ W[N,K]^T + bias, head layout --
__global__ void proj_gemm(const float* __restrict__ A, const float* __restrict__ W,
                          const float* __restrict__ bias, float* __restrict__ out,
                          int M, int K, int Sseg) {
    __shared__ float As[16][68];
    __shared__ float Bs[16][68];
    int tid = threadIdx.x;
    int tx = tid & 15, ty = tid >> 4;
    int m0 = blockIdx.y * 64;
    int n0 = blockIdx.x * 64;
    int lr = tid >> 2;
    int lc = (tid & 3) << 2;
    float acc[4][4] = {};
    for (int k0 = 0; k0 < K; k0 += 16) {
        float4 av = *(const float4*)(A + (size_t)(m0 + lr) * K + k0 + lc);
        float4 bv = *(const float4*)(W + (size_t)(n0 + lr) * K + k0 + lc);
        As[lc+0][lr] = av.x; As[lc+1][lr] = av.y; As[lc+2][lr] = av.z; As[lc+3][lr] = av.w;
        Bs[lc+0][lr] = bv.x; Bs[lc+1][lr] = bv.y; Bs[lc+2][lr] = bv.z; Bs[lc+3][lr] = bv.w;
        __syncthreads();
        TILE_COMPUTE(acc, As, Bs, ty, tx);
        __syncthreads();
    }
    #pragma unroll
    for (int r = 0; r < 4; r++)
        #pragma unroll
        for (int c = 0; c < 4; c++) {
            int m = m0 + ty * 4 + r, n = n0 + tx * 4 + c;
            float val = acc[r][c] + bias[n];
            int b = m / Sseg, s = m - b * Sseg;
            int h = n >> 6, dd = n & 63;
            out[(((size_t)(b * NH + h)) * Sseg + s) * DH + dd] = val;
        }
}

// ---------------- 2) c2p/p2c att: batched C[S,512] = alpha * A @ posX[h]^T ----
__global__ void cp_gemm(const float* __restrict__ Aall, const float* __restrict__ Ball,
                        float* __restrict__ Call, float alpha) {
    __shared__ float As[16][68];
    __shared__ float Bs[16][68];
    int z = blockIdx.z;
    const float* A  = Aall + (size_t)z * SEQ * DH;
    const float* Bp = Ball + (size_t)(z & (NH - 1)) * TWOSPAN * DH;
    float* C = Call + (size_t)z * SEQ * TWOSPAN;
    int tid = threadIdx.x;
    int tx = tid & 15, ty = tid >> 4;
    int m0 = blockIdx.y * 64;
    int n0 = blockIdx.x * 64;
    int lr = tid >> 2;
    int lc = (tid & 3) << 2;
    float acc[4][4] = {};
    for (int k0 = 0; k0 < DH; k0 += 16) {
        float4 av = *(const float4*)(A  + (size_t)(m0 + lr) * DH + k0 + lc);
        float4 bv = *(const float4*)(Bp + (size_t)(n0 + lr) * DH + k0 + lc);
        As[lc+0][lr] = av.x; As[lc+1][lr] = av.y; As[lc+2][lr] = av.z; As[lc+3][lr] = av.w;
        Bs[lc+0][lr] = bv.x; Bs[lc+1][lr] = bv.y; Bs[lc+2][lr] = bv.z; Bs[lc+3][lr] = bv.w;
        __syncthreads();
        TILE_COMPUTE(acc, As, Bs, ty, tx);
        __syncthreads();
    }
    #pragma unroll
    for (int r = 0; r < 4; r++)
        #pragma unroll
        for (int c = 0; c < 4; c++) {
            int m = m0 + ty * 4 + r, n = n0 + tx * 4 + c;
            C[(size_t)m * TWOSPAN + n] = acc[r][c] * alpha;
        }
}

// ---------------- 3) scores: alpha*QK^T + gather(c2p) + gather(p2c) ----------
__global__ void score_gemm(const float* __restrict__ Q, const float* __restrict__ Kh,
                           const float* __restrict__ c2p, const float* __restrict__ p2c,
                           float* __restrict__ Sc, float alpha) {
    __shared__ float As[16][68];
    __shared__ float Bs[16][68];
    int z = blockIdx.z;
    const float* A = Q  + (size_t)z * SEQ * DH;
    const float* B = Kh + (size_t)z * SEQ * DH;
    const float* c2pz = c2p + (size_t)z * SEQ * TWOSPAN;
    const float* p2cz = p2c + (size_t)z * SEQ * TWOSPAN;
    float* C = Sc + (size_t)z * SEQ * SEQ;
    int tid = threadIdx.x;
    int tx = tid & 15, ty = tid >> 4;
    int m0 = blockIdx.y * 64;
    int n0 = blockIdx.x * 64;
    int lr = tid >> 2;
    int lc = (tid & 3) << 2;
    float acc[4][4] = {};
    for (int k0 = 0; k0 < DH; k0 += 16) {
        float4 av = *(const float4*)(A + (size_t)(m0 + lr) * DH + k0 + lc);
        float4 bv = *(const float4*)(B + (size_t)(n0 + lr) * DH + k0 + lc);
        As[lc+0][lr] = av.x; As[lc+1][lr] = av.y; As[lc+2][lr] = av.z; As[lc+3][lr] = av.w;
        Bs[lc+0][lr] = bv.x; Bs[lc+1][lr] = bv.y; Bs[lc+2][lr] = bv.z; Bs[lc+3][lr] = bv.w;
        __syncthreads();
        TILE_COMPUTE(acc, As, Bs, ty, tx);
        __syncthreads();
    }
    #pragma unroll
    for (int r = 0; r < 4; r++)
        #pragma unroll
        for (int c = 0; c < 4; c++) {
            int i = m0 + ty * 4 + r, j = n0 + tx * 4 + c;
            int rel = rel_bucket(i - j);
            int idx = min(max(rel + SPAN, 0), TWOSPAN - 1);
            // c2p: row i of c2p_att at idx; p2c: row j of p2c_att at the same idx
            float val = acc[r][c] * alpha
                      + c2pz[(size_t)i * TWOSPAN + idx]
                      + p2cz[(size_t)j * TWOSPAN + idx];
            C[(size_t)i * SEQ + j] = val;
        }
}

// ---------------- 4) masked softmax (row-wise, in-place) ---------------------
__global__ void softmax_k(float* __restrict__ Sc, const int* __restrict__ mask) {
    __shared__ float sh[32];
    int row = blockIdx.x;             // z*1024 + i
    int b = row >> 14;
    int i = row & 1023;
    float* p = Sc + (size_t)row * SEQ;
    const int* mrow = mask + ((size_t)b << 20) + ((size_t)i << 10);
    int t = threadIdx.x;
    float4 v = *(const float4*)(p + t * 4);
    int4  mm = *(const int4*)(mrow + t * 4);
    const float NEG = -3.402823466e38f;
    float x0 = mm.x ? v.x : NEG;
    float x1 = mm.y ? v.y : NEG;
    float x2 = mm.z ? v.z : NEG;
    float x3 = mm.w ? v.w : NEG;
    float mx = block_max(fmaxf(fmaxf(x0, x1), fmaxf(x2, x3)), sh);
    float e0 = expf(x0 - mx), e1 = expf(x1 - mx), e2 = expf(x2 - mx), e3 = expf(x3 - mx);
    float s = block_sum(e0 + e1 + e2 + e3, sh);
    float inv = 1.0f / s;
    float4 o;
    o.x = mm.x ? e0 * inv : 0.0f;
    o.y = mm.y ? e1 * inv : 0.0f;
    o.z = mm.z ? e2 * inv : 0.0f;
    o.w = mm.w ? e3 * inv : 0.0f;
    *(float4*)(p + t * 4) = o;
}

// ---------------- 5) ctx = probs @ V (AB form), merged-head layout -----------
__global__ void av_gemm(const float* __restrict__ P, const float* __restrict__ V,
                        float* __restrict__ ctx) {
    __shared__ float As[16][68];
    __shared__ float Bs[16][64];
    int z = blockIdx.y;
    const float* A  = P + (size_t)z * SEQ * SEQ;
    const float* Bv = V + (size_t)z * SEQ * DH;
    int b = z >> 4, h = z & 15;
    float* C = ctx + (size_t)b * SEQ * DMODEL + h * DH;
    int tid = threadIdx.x;
    int tx = tid & 15, ty = tid >> 4;
    int m0 = blockIdx.x * 64;
    int lr = tid >> 2;
    int lc = (tid & 3) << 2;
    int kr = tid >> 4;              // 0..15
    int nc = (tid & 15) << 2;       // 0..60
    float acc[4][4] = {};
    for (int k0 = 0; k0 < SEQ; k0 += 16) {
        float4 av = *(const float4*)(A + (size_t)(m0 + lr) * SEQ + k0 + lc);
        As[lc+0][lr] = av.x; As[lc+1][lr] = av.y; As[lc+2][lr] = av.z; As[lc+3][lr] = av.w;
        *(float4*)&Bs[kr][nc] = *(const float4*)(Bv + (size_t)(k0 + kr) * DH + nc);
        __syncthreads();
        TILE_COMPUTE(acc, As, Bs, ty, tx);
        __syncthreads();
    }
    #pragma unroll
    for (int r = 0; r < 4; r++)
        #pragma unroll
        for (int c = 0; c < 4; c++) {
            int m = m0 + ty * 4 + r, n = tx * 4 + c;
            C[(size_t)m * DMODEL + n] = acc[r][c];
        }
}

// ---------------- 6) out = ctx @ Wo^T + bo + residual ------------------------
__global__ void out_gemm(const float* __restrict__ A, const float* __restrict__ W,
                         const float* __restrict__ bias, const float* __restrict__ res,
                         float* __restrict__ out) {
    __shared__ float As[16][68];
    __shared__ float Bs[16][68];
    int tid = threadIdx.x;
    int tx = tid & 15, ty = tid >> 4;
    int m0 = blockIdx.y * 64;
    int n0 = blockIdx.x * 64;
    int lr = tid >> 2;
    int lc = (tid & 3) << 2;
    float acc[4][4] = {};
    for (int k0 = 0; k0 < DMODEL; k0 += 16) {
        float4 av = *(const float4*)(A + (size_t)(m0 + lr) * DMODEL + k0 + lc);
        float4 bv = *(const float4*)(W + (size_t)(n0 + lr) * DMODEL + k0 + lc);
        As[lc+0][lr] = av.x; As[lc+1][lr] = av.y; As[lc+2][lr] = av.z; As[lc+3][lr] = av.w;
        Bs[lc+0][lr] = bv.x; Bs[lc+1][lr] = bv.y; Bs[lc+2][lr] = bv.z; Bs[lc+3][lr] = bv.w;
        __syncthreads();
        TILE_COMPUTE(acc, As, Bs, ty, tx);
        __syncthreads();
    }
    #pragma unroll
    for (int r = 0; r < 4; r++)
        #pragma unroll
        for (int c = 0; c < 4; c++) {
            int m = m0 + ty * 4 + r, n = n0 + tx * 4 + c;
            out[(size_t)m * DMODEL + n] = acc[r][c] + bias[n] + res[(size_t)m * DMODEL + n];
        }
}

// ---------------- 7) LayerNorm (in-place on d_out) ---------------------------
__global__ void ln_k(float* __restrict__ out, const float* __restrict__ gamma,
                     const float* __restrict__ beta) {
    __shared__ float sh[32];
    int row = blockIdx.x, t = threadIdx.x;
    float* p = out + (size_t)row * DMODEL;
    float4 v = *(const float4*)(p + t * 4);
    float mean = block_sum(v.x + v.y + v.z + v.w, sh) * (1.0f / DMODEL);
    float dx = v.x - mean, dy = v.y - mean, dz = v.z - mean, dw = v.w - mean;
    float var = block_sum(dx * dx + dy * dy + dz * dz + dw * dw, sh) * (1.0f / DMODEL);
    float inv = rsqrtf(var + 1e-7f);
    float4 g = *(const float4*)(gamma + t * 4);
    float4 bb = *(const float4*)(beta + t * 4);
    float4 o;
    o.x = dx * inv * g.x + bb.x;
    o.y = dy * inv * g.y + bb.y;
    o.z = dz * inv * g.z + bb.z;
    o.w = dw * inv * g.w + bb.w;
    *(float4*)(p + t * 4) = o;
}

// ---------------- launch ------------------------------------------------------
extern "C" void kernel_launch(void* const* d_in, const int* in_sizes, int n_in,
                              void* d_out, int out_size) {
    const float* hidden = (const float*)d_in[0];
    const int*   mask   = (const int*)  d_in[1];
    const float* rel    = (const float*)d_in[2];
    const float* Wq     = (const float*)d_in[3];
    const float* bq     = (const float*)d_in[4];
    const float* Wk     = (const float*)d_in[5];
    const float* bk     = (const float*)d_in[6];
    const float* Wv     = (const float*)d_in[7];
    const float* bv     = (const float*)d_in[8];
    const float* Wo     = (const float*)d_in[9];
    const float* bo     = (const float*)d_in[10];
    const float* gamma  = (const float*)d_in[11];
    const float* beta   = (const float*)d_in[12];
    float* out = (float*)d_out;

    float *q, *k, *v, *pk, *pq, *c2p, *p2c, *sc, *ctx;
    cudaGetSymbolAddress((void**)&q,   g_q);
    cudaGetSymbolAddress((void**)&k,   g_k);
    cudaGetSymbolAddress((void**)&v,   g_v);
    cudaGetSymbolAddress((void**)&pk,  g_posk);
    cudaGetSymbolAddress((void**)&pq,  g_posq);
    cudaGetSymbolAddress((void**)&c2p, g_c2p);
    cudaGetSymbolAddress((void**)&p2c, g_p2c);
    cudaGetSymbolAddress((void**)&sc,  g_sc);
    cudaGetSymbolAddress((void**)&ctx, g_ctx);

    const float alpha = 1.0f / sqrtf((float)(DH * 3));   // 1/sqrt(192)
    dim3 thr(256);

    proj_gemm<<<dim3(16, 64), thr>>>(hidden, Wq, bq, q, BDIM * SEQ, DMODEL, SEQ);
    proj_gemm<<<dim3(16, 64), thr>>>(hidden, Wk, bk, k, BDIM * SEQ, DMODEL, SEQ);
    proj_gemm<<<dim3(16, 64), thr>>>(hidden, Wv, bv, v, BDIM * SEQ, DMODEL, SEQ);
    proj_gemm<<<dim3(16, 8),  thr>>>(rel, Wk, bk, pk, TWOSPAN, DMODEL, TWOSPAN);
    proj_gemm<<<dim3(16, 8),  thr>>>(rel, Wq, bq, pq, TWOSPAN, DMODEL, TWOSPAN);

    cp_gemm<<<dim3(8, 16, NBATCH), thr>>>(q, pk, c2p, alpha);
    cp_gemm<<<dim3(8, 16, NBATCH), thr>>>(k, pq, p2c, alpha);

    score_gemm<<<dim3(16, 16, NBATCH), thr>>>(q, k, c2p, p2c, sc, alpha);

    softmax_k<<<NBATCH * SEQ, 256>>>(sc, mask);

    av_gemm<<<dim3(16, NBATCH), thr>>>(sc, v, ctx);

    out_gemm<<<dim3(16, 64), thr>>>(ctx, Wo, bo, hidden, out);

    ln_k<<<BDIM * SEQ, 256>>>(out, gamma, beta);
}